// round 1
// baseline (speedup 1.0000x reference)
#include <cuda_runtime.h>
#include <math.h>

// ---------------- problem constants ----------------
#define B_   256
#define CIN_ 22
#define T_   1000
// stage1 (fused conv_time+conv_spat): Cout=25, K=10, Tconv=991, Tpool=330
// stage2: 25->50, K=10, Tin=330, Tconv=321, Tpool=107
// stage3: 50->100, K=10, Tin=107, Tconv=98, Tpool=32
// stage4: 100->200, K=10, Tin=32, Tconv=23, Tpool=7
// feat = 200*7 = 1400, heads: K=10 subjects, O=4

// ---------------- device scratch (no allocation allowed) ----------------
__device__ float g_Weff[25 * 220];          // [p][c*10+k]
__device__ float g_beff[25];
__device__ float g_y1[B_ * 25 * 330];
__device__ float g_y2[B_ * 50 * 107];
__device__ float g_y3[B_ * 100 * 32];
__device__ float g_feat[B_ * 1400];

__device__ __forceinline__ float elu1(float x) {
    return x > 0.f ? x : expm1f(x);
}

// ---------------- kernel 0: fold conv_time into conv_spat ----------------
__global__ void precompute_k(const float* __restrict__ w_time,   // [25][10]
                             const float* __restrict__ b_time,   // [25]
                             const float* __restrict__ w_spat,   // [25][25][22]
                             const float* __restrict__ b_spat)   // [25]
{
    for (int idx = threadIdx.x; idx < 25 * 220; idx += blockDim.x) {
        int p = idx / 220, rem = idx % 220, c = rem / 10, k = rem % 10;
        float s = 0.f;
        #pragma unroll
        for (int o = 0; o < 25; o++)
            s = fmaf(w_spat[p * 550 + o * 22 + c], w_time[o * 10 + k], s);
        g_Weff[idx] = s;
    }
    if (threadIdx.x < 25) {
        int p = threadIdx.x;
        float s = b_spat[p];
        for (int o = 0; o < 25; o++) {
            float w = 0.f;
            for (int c = 0; c < 22; c++) w += w_spat[p * 550 + o * 22 + c];
            s = fmaf(b_time[o], w, s);
        }
        g_beff[p] = s;
    }
}

// ---------------- stage 1: x[256,22,1000] -> y1[256,25,330] ----------------
// smem: xs 22000 + ws 5500 + bs 25 floats = 110,100 B
__global__ __launch_bounds__(256) void stage1_k(const float* __restrict__ x)
{
    extern __shared__ float sm[];
    float* xs = sm;               // [22][1000]
    float* ws = sm + 22000;       // [25][220]
    float* bs = ws + 5500;        // [25]
    const int b = blockIdx.x;
    const float* xb = x + b * (CIN_ * T_);
    for (int i = threadIdx.x; i < CIN_ * T_; i += blockDim.x) xs[i] = xb[i];
    for (int i = threadIdx.x; i < 5500; i += blockDim.x) ws[i] = g_Weff[i];
    if (threadIdx.x < 25) bs[threadIdx.x] = g_beff[threadIdx.x];
    __syncthreads();

    for (int tp = threadIdx.x; tp < 330; tp += blockDim.x) {
        const int t0 = 3 * tp;
        #pragma unroll
        for (int pass = 0; pass < 2; pass++) {
            const int P0 = pass ? 13 : 0;
            const int PT = pass ? 12 : 13;
            float acc[13 * 3];
            #pragma unroll
            for (int i = 0; i < 13 * 3; i++) acc[i] = 0.f;
            for (int c = 0; c < 22; c++) {
                float xr[12];
                #pragma unroll
                for (int i = 0; i < 12; i++) xr[i] = xs[c * 1000 + t0 + i];
                #pragma unroll
                for (int k = 0; k < 10; k++) {
                    #pragma unroll
                    for (int p = 0; p < 13; p++) {
                        if (p < PT) {
                            float wv = ws[(P0 + p) * 220 + c * 10 + k];
                            acc[p * 3 + 0] = fmaf(wv, xr[k + 0], acc[p * 3 + 0]);
                            acc[p * 3 + 1] = fmaf(wv, xr[k + 1], acc[p * 3 + 1]);
                            acc[p * 3 + 2] = fmaf(wv, xr[k + 2], acc[p * 3 + 2]);
                        }
                    }
                }
            }
            #pragma unroll
            for (int p = 0; p < 13; p++) {
                if (p < PT) {
                    float m = fmaxf(acc[p * 3], fmaxf(acc[p * 3 + 1], acc[p * 3 + 2])) + bs[P0 + p];
                    g_y1[b * (25 * 330) + (P0 + p) * 330 + tp] = elu1(m);
                }
            }
        }
    }
}

// ---------------- stage 2: y1[256,25,330] -> y2[256,50,107] ----------------
// smem: xs 8250 + ws 12500 + 0 = 83,000 B
__global__ __launch_bounds__(256) void stage2_k(const float* __restrict__ w2,   // [50][25][10]
                                                const float* __restrict__ b2)   // [50]
{
    extern __shared__ float sm[];
    float* xs = sm;               // [25][330]
    float* ws = sm + 8250;        // [50][250]
    const int b = blockIdx.x;
    const float* xb = g_y1 + b * (25 * 330);
    for (int i = threadIdx.x; i < 25 * 330; i += blockDim.x) xs[i] = xb[i];
    for (int i = threadIdx.x; i < 12500; i += blockDim.x) ws[i] = w2[i];
    __syncthreads();

    const int tp = threadIdx.x & 127;
    const int oh = threadIdx.x >> 7;   // 0/1 -> channels [0,25) / [25,50)
    if (tp >= 107) return;
    const int t0 = 3 * tp;
    #pragma unroll
    for (int pass = 0; pass < 2; pass++) {
        const int P0 = oh * 25 + (pass ? 13 : 0);
        const int PT = pass ? 12 : 13;
        float acc[13 * 3];
        #pragma unroll
        for (int i = 0; i < 13 * 3; i++) acc[i] = 0.f;
        for (int c = 0; c < 25; c++) {
            float xr[12];
            #pragma unroll
            for (int i = 0; i < 12; i++) xr[i] = xs[c * 330 + t0 + i];
            #pragma unroll
            for (int k = 0; k < 10; k++) {
                #pragma unroll
                for (int p = 0; p < 13; p++) {
                    if (p < PT) {
                        float wv = ws[(P0 + p) * 250 + c * 10 + k];
                        acc[p * 3 + 0] = fmaf(wv, xr[k + 0], acc[p * 3 + 0]);
                        acc[p * 3 + 1] = fmaf(wv, xr[k + 1], acc[p * 3 + 1]);
                        acc[p * 3 + 2] = fmaf(wv, xr[k + 2], acc[p * 3 + 2]);
                    }
                }
            }
        }
        #pragma unroll
        for (int p = 0; p < 13; p++) {
            if (p < PT) {
                float m = fmaxf(acc[p * 3], fmaxf(acc[p * 3 + 1], acc[p * 3 + 2])) + __ldg(&b2[P0 + p]);
                g_y2[b * (50 * 107) + (P0 + p) * 107 + tp] = elu1(m);
            }
        }
    }
}

// ---------------- stage 3: y2[256,50,107] -> y3[256,100,32] ----------------
// grid (256, 2): blockIdx.y = half of output channels (50 each)
// smem: xs 5350 + ws 25000 = 121,400 B
__global__ __launch_bounds__(256) void stage3_k(const float* __restrict__ w3,   // [100][50][10]
                                                const float* __restrict__ b3)   // [100]
{
    extern __shared__ float sm[];
    float* xs = sm;               // [50][107]
    float* ws = sm + 5350;        // [50][500] (this half)
    const int b = blockIdx.x;
    const int half = blockIdx.y;  // 0/1
    const float* xb = g_y2 + b * (50 * 107);
    for (int i = threadIdx.x; i < 50 * 107; i += blockDim.x) xs[i] = xb[i];
    for (int i = threadIdx.x; i < 25000; i += blockDim.x) ws[i] = w3[half * 25000 + i];
    __syncthreads();

    const int tp = threadIdx.x & 31;       // 0..31 (exactly Tpool)
    const int oy = threadIdx.x >> 5;       // 0..7
    // 50 channels split 7,7,6,6,6,6,6,6 over 8 groups
    const int PT = (oy < 2) ? 7 : 6;
    const int P0 = (oy < 2) ? 7 * oy : 14 + 6 * (oy - 2);
    const int t0 = 3 * tp;

    float acc[7 * 3];
    #pragma unroll
    for (int i = 0; i < 7 * 3; i++) acc[i] = 0.f;
    for (int c = 0; c < 50; c++) {
        float xr[12];
        #pragma unroll
        for (int i = 0; i < 12; i++) xr[i] = xs[c * 107 + t0 + i];
        #pragma unroll
        for (int k = 0; k < 10; k++) {
            #pragma unroll
            for (int p = 0; p < 7; p++) {
                if (p < PT) {
                    float wv = ws[(P0 + p) * 500 + c * 10 + k];
                    acc[p * 3 + 0] = fmaf(wv, xr[k + 0], acc[p * 3 + 0]);
                    acc[p * 3 + 1] = fmaf(wv, xr[k + 1], acc[p * 3 + 1]);
                    acc[p * 3 + 2] = fmaf(wv, xr[k + 2], acc[p * 3 + 2]);
                }
            }
        }
    }
    #pragma unroll
    for (int p = 0; p < 7; p++) {
        if (p < PT) {
            int og = half * 50 + P0 + p;
            float m = fmaxf(acc[p * 3], fmaxf(acc[p * 3 + 1], acc[p * 3 + 2])) + __ldg(&b3[og]);
            g_y3[b * (100 * 32) + og * 32 + tp] = elu1(m);
        }
    }
}

// ---------------- stage 4: y3[256,100,32] -> feat[256,1400] ----------------
// weights 800KB -> streamed from L2 via __ldg float2 (lane-uniform over tp lanes)
// smem: xs 3200 floats = 12,800 B
__global__ __launch_bounds__(256) void stage4_k(const float* __restrict__ w4,   // [200][100][10]
                                                const float* __restrict__ b4)   // [200]
{
    extern __shared__ float sm[];
    float* xs = sm;               // [100][32]
    const int b = blockIdx.x;
    const float* xb = g_y3 + b * (100 * 32);
    for (int i = threadIdx.x; i < 100 * 32; i += blockDim.x) xs[i] = xb[i];
    __syncthreads();

    const int tp = threadIdx.x & 7;        // 0..7, only <7 valid
    const int oy = threadIdx.x >> 3;       // 0..31
    if (tp >= 7) return;
    const int t0 = 3 * tp;

    #pragma unroll 1
    for (int r = 0; r < 7; r++) {
        const int o = 32 * r + oy;
        if (o >= 200) break;
        float a0 = 0.f, a1 = 0.f, a2 = 0.f;
        const float* wrow = w4 + o * 1000;
        for (int c = 0; c < 100; c++) {
            float xr[12];
            #pragma unroll
            for (int i = 0; i < 12; i++) xr[i] = xs[c * 32 + t0 + i];
            // 10 weights = 5 x float2 (8B aligned: offset 40*c bytes)
            const float2* wp = reinterpret_cast<const float2*>(wrow + c * 10);
            #pragma unroll
            for (int k2 = 0; k2 < 5; k2++) {
                float2 wv = __ldg(&wp[k2]);
                int k = 2 * k2;
                a0 = fmaf(wv.x, xr[k + 0], a0);
                a1 = fmaf(wv.x, xr[k + 1], a1);
                a2 = fmaf(wv.x, xr[k + 2], a2);
                a0 = fmaf(wv.y, xr[k + 1], a0);
                a1 = fmaf(wv.y, xr[k + 2], a1);
                a2 = fmaf(wv.y, xr[k + 3], a2);
            }
        }
        float m = fmaxf(a0, fmaxf(a1, a2)) + __ldg(&b4[o]);
        g_feat[b * 1400 + o * 7 + tp] = elu1(m);   // reshape [B,200,7] -> [B,1400]
    }
}

// ---------------- head: per-sample routed linear [1400] -> [4] ----------------
__global__ void head_k(const int* __restrict__ sid,
                       const float* __restrict__ hW,   // [10][4][1400]
                       const float* __restrict__ hB,   // [10][4]
                       float* __restrict__ out)        // [256][4]
{
    const int b = blockIdx.x;
    const int s = sid[b];
    const float* f = g_feat + b * 1400;
    const float* W = hW + s * (4 * 1400);
    float acc[4] = {0.f, 0.f, 0.f, 0.f};
    for (int i = threadIdx.x; i < 1400; i += blockDim.x) {
        float fv = f[i];
        #pragma unroll
        for (int o = 0; o < 4; o++) acc[o] = fmaf(fv, __ldg(&W[o * 1400 + i]), acc[o]);
    }
    #pragma unroll
    for (int off = 16; off > 0; off >>= 1) {
        #pragma unroll
        for (int o = 0; o < 4; o++) acc[o] += __shfl_down_sync(0xFFFFFFFFu, acc[o], off);
    }
    __shared__ float red[4][4];
    const int w = threadIdx.x >> 5, l = threadIdx.x & 31;
    if (l == 0) {
        #pragma unroll
        for (int o = 0; o < 4; o++) red[o][w] = acc[o];
    }
    __syncthreads();
    if (threadIdx.x < 4) {
        int o = threadIdx.x;
        float sum = red[o][0] + red[o][1] + red[o][2] + red[o][3];
        out[b * 4 + o] = sum + __ldg(&hB[s * 4 + o]);
    }
}

// ---------------- launch ----------------
extern "C" void kernel_launch(void* const* d_in, const int* in_sizes, int n_in,
                              void* d_out, int out_size)
{
    const float* x      = (const float*)d_in[0];
    const int*   sid    = (const int*)  d_in[1];
    const float* w_time = (const float*)d_in[2];
    const float* b_time = (const float*)d_in[3];
    const float* w_spat = (const float*)d_in[4];
    const float* b_spat = (const float*)d_in[5];
    const float* w2     = (const float*)d_in[6];
    const float* b2     = (const float*)d_in[7];
    const float* w3     = (const float*)d_in[8];
    const float* b3     = (const float*)d_in[9];
    const float* w4     = (const float*)d_in[10];
    const float* b4     = (const float*)d_in[11];
    const float* hW     = (const float*)d_in[12];
    const float* hB     = (const float*)d_in[13];
    float* out = (float*)d_out;

    const int smem1 = (22000 + 5500 + 25) * 4;      // 110,100 B
    const int smem2 = (8250 + 12500) * 4;           //  83,000 B
    const int smem3 = (5350 + 25000) * 4;           // 121,400 B
    const int smem4 = (3200) * 4;                   //  12,800 B
    cudaFuncSetAttribute(stage1_k, cudaFuncAttributeMaxDynamicSharedMemorySize, smem1);
    cudaFuncSetAttribute(stage2_k, cudaFuncAttributeMaxDynamicSharedMemorySize, smem2);
    cudaFuncSetAttribute(stage3_k, cudaFuncAttributeMaxDynamicSharedMemorySize, smem3);

    precompute_k<<<1, 256>>>(w_time, b_time, w_spat, b_spat);
    stage1_k<<<B_, 256, smem1>>>(x);
    stage2_k<<<B_, 256, smem2>>>(w2, b2);
    stage3_k<<<dim3(B_, 2), 256, smem3>>>(w3, b3);
    stage4_k<<<B_, 256, smem4>>>(w4, b4);
    head_k<<<B_, 128>>>(sid, hW, hB, out);
}

// round 2
// speedup vs baseline: 1.1430x; 1.1430x over previous
#include <cuda_runtime.h>
#include <math.h>

#define B_ 256

// ---------------- device scratch ----------------
__device__ float g_Weff[25 * 220];          // [p][c*10+k]
__device__ float g_beff[25];
__device__ float g_y1[B_ * 25 * 330];
__device__ float g_y2[B_ * 50 * 107];
__device__ float g_y3[B_ * 100 * 32];
__device__ float g_feat[B_ * 1400];

__device__ __forceinline__ float elu1(float x) {
    return x > 0.f ? x : expm1f(x);
}

// ---------------- kernel 0: fold conv_time into conv_spat ----------------
__global__ void precompute_k(const float* __restrict__ w_time,   // [25][10]
                             const float* __restrict__ b_time,   // [25]
                             const float* __restrict__ w_spat,   // [25][25][22]
                             const float* __restrict__ b_spat)   // [25]
{
    for (int idx = threadIdx.x; idx < 25 * 220; idx += blockDim.x) {
        int p = idx / 220, rem = idx % 220, c = rem / 10, k = rem % 10;
        float s = 0.f;
        #pragma unroll
        for (int o = 0; o < 25; o++)
            s = fmaf(w_spat[p * 550 + o * 22 + c], w_time[o * 10 + k], s);
        g_Weff[idx] = s;
    }
    if (threadIdx.x < 25) {
        int p = threadIdx.x;
        float s = b_spat[p];
        for (int o = 0; o < 25; o++) {
            float w = 0.f;
            for (int c = 0; c < 22; c++) w += w_spat[p * 550 + o * 22 + c];
            s = fmaf(b_time[o], w, s);
        }
        g_beff[p] = s;
    }
}

// ---------------- generic conv+pool inner bodies ----------------
// weights in smem padded to 12 floats per (p,c): float4/float4/float2 loads.
// single sample, 3 pooled positions, P output channels, C input channels
template<int P, int C, int XS, int WS>
__device__ __forceinline__ void conv_acc(const float* __restrict__ xs,
                                         const float* __restrict__ ws,
                                         float* __restrict__ acc)
{
    #pragma unroll
    for (int i = 0; i < P * 3; i++) acc[i] = 0.f;
    #pragma unroll 1
    for (int c = 0; c < C; c++) {
        float xr[12];
        #pragma unroll
        for (int i = 0; i < 12; i++) xr[i] = xs[c * XS + i];
        #pragma unroll
        for (int p = 0; p < P; p++) {
            const float* wp = ws + p * WS + c * 12;
            float4 w0 = *reinterpret_cast<const float4*>(wp);
            float4 w1 = *reinterpret_cast<const float4*>(wp + 4);
            float2 w2 = *reinterpret_cast<const float2*>(wp + 8);
            float wk[10] = {w0.x, w0.y, w0.z, w0.w, w1.x, w1.y, w1.z, w1.w, w2.x, w2.y};
            #pragma unroll
            for (int k = 0; k < 10; k++) {
                acc[p * 3 + 0] = fmaf(wk[k], xr[k + 0], acc[p * 3 + 0]);
                acc[p * 3 + 1] = fmaf(wk[k], xr[k + 1], acc[p * 3 + 1]);
                acc[p * 3 + 2] = fmaf(wk[k], xr[k + 2], acc[p * 3 + 2]);
            }
        }
    }
}

// two samples per thread (weight load amortized over 6 FMAs)
template<int P, int C, int XS, int WS>
__device__ __forceinline__ void conv_acc2(const float* __restrict__ x0,
                                          const float* __restrict__ x1,
                                          const float* __restrict__ ws,
                                          float* __restrict__ acc)
{
    #pragma unroll
    for (int i = 0; i < P * 6; i++) acc[i] = 0.f;
    #pragma unroll 1
    for (int c = 0; c < C; c++) {
        float xa[12], xb[12];
        #pragma unroll
        for (int i = 0; i < 12; i++) { xa[i] = x0[c * XS + i]; xb[i] = x1[c * XS + i]; }
        #pragma unroll
        for (int p = 0; p < P; p++) {
            const float* wp = ws + p * WS + c * 12;
            float4 w0 = *reinterpret_cast<const float4*>(wp);
            float4 w1 = *reinterpret_cast<const float4*>(wp + 4);
            float2 w2 = *reinterpret_cast<const float2*>(wp + 8);
            float wk[10] = {w0.x, w0.y, w0.z, w0.w, w1.x, w1.y, w1.z, w1.w, w2.x, w2.y};
            #pragma unroll
            for (int k = 0; k < 10; k++) {
                acc[p * 6 + 0] = fmaf(wk[k], xa[k + 0], acc[p * 6 + 0]);
                acc[p * 6 + 1] = fmaf(wk[k], xa[k + 1], acc[p * 6 + 1]);
                acc[p * 6 + 2] = fmaf(wk[k], xa[k + 2], acc[p * 6 + 2]);
                acc[p * 6 + 3] = fmaf(wk[k], xb[k + 0], acc[p * 6 + 3]);
                acc[p * 6 + 4] = fmaf(wk[k], xb[k + 1], acc[p * 6 + 4]);
                acc[p * 6 + 5] = fmaf(wk[k], xb[k + 2], acc[p * 6 + 5]);
            }
        }
    }
}

// ---------------- stage 1: x[256,22,1000] -> y1[256,25,330] ----------------
// grid (256, 2) time-halves; smem: xs [22][504] + ws [25][264] = 70,752 B
__global__ __launch_bounds__(352, 2) void stage1_k(const float* __restrict__ x)
{
    extern __shared__ float sm[];
    float* xs = sm;                // [22][504]
    float* ws = sm + 22 * 504;     // [25][264]
    __shared__ float bs[25];
    const int b = blockIdx.x, half = blockIdx.y;
    const int xoff = half * 495;
    const float* xb = x + b * 22000;
    for (int i = threadIdx.x; i < 22 * 504; i += 352) {
        int c = i / 504, t = i - c * 504;
        xs[i] = xb[c * 1000 + xoff + t];
    }
    for (int i = threadIdx.x; i < 5500; i += 352) {
        int p = i / 220, r = i - p * 220;
        int c = r / 10, k = r - c * 10;
        ws[p * 264 + c * 12 + k] = g_Weff[i];
    }
    if (threadIdx.x < 25) bs[threadIdx.x] = g_beff[threadIdx.x];
    __syncthreads();

    const int tpL = threadIdx.x % 176;
    const int pg  = threadIdx.x / 176;
    if (tpL >= 165) return;
    const float* xp = xs + 3 * tpL;
    const int tp = half * 165 + tpL;

    if (pg == 0) {
        float acc[39];
        conv_acc<13, 22, 504, 264>(xp, ws, acc);
        #pragma unroll
        for (int p = 0; p < 13; p++) {
            float m = fmaxf(acc[p * 3], fmaxf(acc[p * 3 + 1], acc[p * 3 + 2])) + bs[p];
            g_y1[b * 8250 + p * 330 + tp] = elu1(m);
        }
    } else {
        float acc[36];
        conv_acc<12, 22, 504, 264>(xp, ws + 13 * 264, acc);
        #pragma unroll
        for (int p = 0; p < 12; p++) {
            float m = fmaxf(acc[p * 3], fmaxf(acc[p * 3 + 1], acc[p * 3 + 2])) + bs[13 + p];
            g_y1[b * 8250 + (13 + p) * 330 + tp] = elu1(m);
        }
    }
}

// ---------------- stage 2: y1[256,25,330] -> y2[256,50,107] ----------------
// grid (256, 2) channel-halves; smem: xs 8252 + ws [25][300] = 63,008 B
__global__ __launch_bounds__(448, 2) void stage2_k(const float* __restrict__ w2,   // [50][25][10]
                                                   const float* __restrict__ b2)   // [50]
{
    extern __shared__ float sm[];
    float* xs = sm;            // [25][330] (+2 pad for alignment)
    float* ws = sm + 8252;     // [25][300]
    const int b = blockIdx.x, half = blockIdx.y;
    const float* xb = g_y1 + b * 8250;
    for (int i = threadIdx.x; i < 8250; i += 448) xs[i] = xb[i];
    for (int i = threadIdx.x; i < 6250; i += 448) {
        int p = i / 250, r = i - p * 250;
        int c = r / 10, k = r - c * 10;
        ws[p * 300 + c * 12 + k] = w2[(half * 25 + p) * 250 + r];
    }
    __syncthreads();

    const int tp = threadIdx.x % 112;
    const int pg = threadIdx.x / 112;   // 0..3 -> channel groups 7,6,6,6
    if (tp >= 107) return;
    const float* xp = xs + 3 * tp;
    const int P0 = (pg == 0) ? 0 : 7 + 6 * (pg - 1);
    const int P  = (pg == 0) ? 7 : 6;

    float acc[21];
    if (pg == 0) conv_acc<7, 25, 330, 300>(xp, ws, acc);
    else         conv_acc<6, 25, 330, 300>(xp, ws + P0 * 300, acc);

    for (int p = 0; p < P; p++) {
        int och = half * 25 + P0 + p;
        float m = fmaxf(acc[p * 3], fmaxf(acc[p * 3 + 1], acc[p * 3 + 2])) + __ldg(&b2[och]);
        g_y2[b * 5350 + och * 107 + tp] = elu1(m);
    }
}

// ---------------- stage 3: y2[256,50,107] -> y3[256,100,32] ----------------
// grid (128 sample-pairs, 4 channel-quarters); smem: xs 2*5350 + ws [25][600] = 102,800 B
__global__ __launch_bounds__(256, 2) void stage3_k(const float* __restrict__ w3,   // [100][50][10]
                                                   const float* __restrict__ b3)   // [100]
{
    extern __shared__ float sm[];
    float* xs = sm;             // [2][50][107]
    float* ws = sm + 10700;     // [25][600]
    const int sp = blockIdx.x, cg = blockIdx.y;
    const int s0 = sp * 2;
    for (int i = threadIdx.x; i < 10700; i += 256) {
        int s = i / 5350, r = i - s * 5350;
        xs[i] = g_y2[(s0 + s) * 5350 + r];
    }
    for (int i = threadIdx.x; i < 12500; i += 256) {
        int p = i / 500, r = i - p * 500;
        int c = r / 10, k = r - c * 10;
        ws[p * 600 + c * 12 + k] = w3[(cg * 25 + p) * 500 + r];
    }
    __syncthreads();

    const int tp = threadIdx.x & 31;
    const int g  = threadIdx.x >> 5;   // 0..7 -> channel groups 4,3,3,3,3,3,3,3
    const float* x0 = xs + 3 * tp;
    const float* x1 = xs + 5350 + 3 * tp;

    float acc[24];
    int P0, P;
    if (g == 0) {
        P0 = 0; P = 4;
        conv_acc2<4, 50, 107, 600>(x0, x1, ws, acc);
    } else {
        P0 = 4 + 3 * (g - 1); P = 3;
        conv_acc2<3, 50, 107, 600>(x0, x1, ws + P0 * 600, acc);
    }

    for (int p = 0; p < P; p++) {
        int og = cg * 25 + P0 + p;
        float bv = __ldg(&b3[og]);
        #pragma unroll
        for (int s = 0; s < 2; s++) {
            float m = fmaxf(acc[p * 6 + s * 3],
                      fmaxf(acc[p * 6 + s * 3 + 1], acc[p * 6 + s * 3 + 2])) + bv;
            g_y3[(s0 + s) * 3200 + og * 32 + tp] = elu1(m);
        }
    }
}

// ---------------- stage 4: y3[256,100,32] -> feat[256,1400] ----------------
// thread-per-output-channel, all 21 conv positions; weights staged in smem chunks
// smem: xs [100][32] + wchunk [50][201] = 53,012 B
__global__ __launch_bounds__(224, 3) void stage4_k(const float* __restrict__ w4,   // [200][100][10]
                                                   const float* __restrict__ b4)   // [200]
{
    extern __shared__ float sm[];
    float* xs = sm;             // [100][32]
    float* wc = sm + 3200;      // [50][201]: (c*10+k)*201 + o
    const int b = blockIdx.x;
    const int o = threadIdx.x;
    for (int i = threadIdx.x; i < 3200; i += 224) xs[i] = g_y3[b * 3200 + i];

    float acc[21];
    #pragma unroll
    for (int i = 0; i < 21; i++) acc[i] = 0.f;

    for (int c0 = 0; c0 < 100; c0 += 5) {
        __syncthreads();
        // stage 5 input channels of weights: 200 o * 50 floats = 5000 float2
        const float2* wg = reinterpret_cast<const float2*>(w4 + c0 * 10);
        for (int i = threadIdx.x; i < 5000; i += 224) {
            int oo = i / 25, r2 = i - oo * 25;
            float2 v = __ldg(&wg[oo * 500 + r2]);   // w4[oo*1000 + c0*10 + 2*r2 ..]
            wc[(2 * r2) * 201 + oo]     = v.x;
            wc[(2 * r2 + 1) * 201 + oo] = v.y;
        }
        __syncthreads();
        if (o < 200) {
            #pragma unroll
            for (int c = 0; c < 5; c++) {
                float xr[32];
                const float4* xp = reinterpret_cast<const float4*>(xs + (c0 + c) * 32);
                #pragma unroll
                for (int q = 0; q < 8; q++) {
                    float4 v = xp[q];
                    xr[q * 4 + 0] = v.x; xr[q * 4 + 1] = v.y;
                    xr[q * 4 + 2] = v.z; xr[q * 4 + 3] = v.w;
                }
                #pragma unroll
                for (int k = 0; k < 10; k++) {
                    float wv = wc[(c * 10 + k) * 201 + o];
                    #pragma unroll
                    for (int j = 0; j < 21; j++)
                        acc[j] = fmaf(wv, xr[j + k], acc[j]);
                }
            }
        }
    }

    if (o < 200) {
        float bo = __ldg(&b4[o]);
        #pragma unroll
        for (int t = 0; t < 7; t++) {
            float m = fmaxf(acc[3 * t], fmaxf(acc[3 * t + 1], acc[3 * t + 2])) + bo;
            g_feat[b * 1400 + o * 7 + t] = elu1(m);
        }
    }
}

// ---------------- head: per-sample routed linear [1400] -> [4] ----------------
__global__ void head_k(const int* __restrict__ sid,
                       const float* __restrict__ hW,   // [10][4][1400]
                       const float* __restrict__ hB,   // [10][4]
                       float* __restrict__ out)        // [256][4]
{
    const int b = blockIdx.x;
    const int s = sid[b];
    const float* f = g_feat + b * 1400;
    const float* W = hW + s * (4 * 1400);
    float acc[4] = {0.f, 0.f, 0.f, 0.f};
    for (int i = threadIdx.x; i < 1400; i += blockDim.x) {
        float fv = f[i];
        #pragma unroll
        for (int o = 0; o < 4; o++) acc[o] = fmaf(fv, __ldg(&W[o * 1400 + i]), acc[o]);
    }
    #pragma unroll
    for (int off = 16; off > 0; off >>= 1) {
        #pragma unroll
        for (int o = 0; o < 4; o++) acc[o] += __shfl_down_sync(0xFFFFFFFFu, acc[o], off);
    }
    __shared__ float red[4][4];
    const int w = threadIdx.x >> 5, l = threadIdx.x & 31;
    if (l == 0) {
        #pragma unroll
        for (int o = 0; o < 4; o++) red[o][w] = acc[o];
    }
    __syncthreads();
    if (threadIdx.x < 4) {
        int o = threadIdx.x;
        float sum = red[o][0] + red[o][1] + red[o][2] + red[o][3];
        out[b * 4 + o] = sum + __ldg(&hB[s * 4 + o]);
    }
}

// ---------------- launch ----------------
extern "C" void kernel_launch(void* const* d_in, const int* in_sizes, int n_in,
                              void* d_out, int out_size)
{
    const float* x      = (const float*)d_in[0];
    const int*   sid    = (const int*)  d_in[1];
    const float* w_time = (const float*)d_in[2];
    const float* b_time = (const float*)d_in[3];
    const float* w_spat = (const float*)d_in[4];
    const float* b_spat = (const float*)d_in[5];
    const float* w2     = (const float*)d_in[6];
    const float* b2     = (const float*)d_in[7];
    const float* w3     = (const float*)d_in[8];
    const float* b3     = (const float*)d_in[9];
    const float* w4     = (const float*)d_in[10];
    const float* b4     = (const float*)d_in[11];
    const float* hW     = (const float*)d_in[12];
    const float* hB     = (const float*)d_in[13];
    float* out = (float*)d_out;

    const int smem1 = (22 * 504 + 25 * 264) * 4;     // 70,752
    const int smem2 = (8252 + 25 * 300) * 4;         // 63,008
    const int smem3 = (10700 + 25 * 600) * 4;        // 102,800
    const int smem4 = (3200 + 50 * 201 + 3) * 4;     // 53,012
    cudaFuncSetAttribute(stage1_k, cudaFuncAttributeMaxDynamicSharedMemorySize, smem1);
    cudaFuncSetAttribute(stage2_k, cudaFuncAttributeMaxDynamicSharedMemorySize, smem2);
    cudaFuncSetAttribute(stage3_k, cudaFuncAttributeMaxDynamicSharedMemorySize, smem3);
    cudaFuncSetAttribute(stage4_k, cudaFuncAttributeMaxDynamicSharedMemorySize, smem4);

    precompute_k<<<1, 256>>>(w_time, b_time, w_spat, b_spat);
    stage1_k<<<dim3(B_, 2), 352, smem1>>>(x);
    stage2_k<<<dim3(B_, 2), 448, smem2>>>(w2, b2);
    stage3_k<<<dim3(128, 4), 256, smem3>>>(w3, b3);
    stage4_k<<<B_, 224, smem4>>>(w4, b4);
    head_k<<<B_, 128>>>(sid, hW, hB, out);
}